// round 11
// baseline (speedup 1.0000x reference)
#include <cuda_runtime.h>
#include <cuda_bf16.h>

// Global accumulator. Zero-initialized; finalize kernel resets it each launch
// so CUDA-graph replays are deterministic.
__device__ float g_accum = 0.0f;

// ---------------------------------------------------------------------------
// Kernel 1: R1 streaming shape (proven ~6.6 TB/s): one CTA per segment,
// 128 threads, 3 front-batched LDG.128 per thread. Tail = ONE fire-and-forget
// RED.ADD per CTA (unused atomicAdd return -> REDG, no round-trip wait).
// ---------------------------------------------------------------------------
__global__ __launch_bounds__(128, 16) void listnet_seg_kernel(
    const float* __restrict__ mean,
    const float* __restrict__ variance,
    const float* __restrict__ targets,
    const int*   __restrict__ scope,
    int seg_len)
{
    const int seg = blockIdx.x;
    const int tid = threadIdx.x;           // 0..127
    const long long base = (long long)seg * seg_len;

    const float4* __restrict__ m4 = reinterpret_cast<const float4*>(mean + base);
    const float4* __restrict__ v4 = reinterpret_cast<const float4*>(variance + base);
    const float4* __restrict__ t4 = reinterpret_cast<const float4*>(targets + base);

    float s1 = 0.0f;  // sum exp(a),  a = x + 0.5 y
    float s2 = 0.0f;  // sum exp(t)
    float s3 = 0.0f;  // sum exp(t) * b,  b = x - 0.5 y

    const int nvec = seg_len >> 2;         // float4s per segment (128 for 512)
    for (int i = tid; i < nvec; i += 128) {
        float4 m = m4[i];
        float4 v = v4[i];
        float4 t = t4[i];

        { float h = 0.5f * v.x; float a = m.x + h, b = m.x - h;
          float ea = __expf(a), et = __expf(t.x);
          s1 += ea; s2 += et; s3 += et * b; }
        { float h = 0.5f * v.y; float a = m.y + h, b = m.y - h;
          float ea = __expf(a), et = __expf(t.y);
          s1 += ea; s2 += et; s3 += et * b; }
        { float h = 0.5f * v.z; float a = m.z + h, b = m.z - h;
          float ea = __expf(a), et = __expf(t.z);
          s1 += ea; s2 += et; s3 += et * b; }
        { float h = 0.5f * v.w; float a = m.w + h, b = m.w - h;
          float ea = __expf(a), et = __expf(t.w);
          s1 += ea; s2 += et; s3 += et * b; }
    }

    // Warp reduction (3 values)
    #pragma unroll
    for (int off = 16; off > 0; off >>= 1) {
        s1 += __shfl_down_sync(0xFFFFFFFFu, s1, off);
        s2 += __shfl_down_sync(0xFFFFFFFFu, s2, off);
        s3 += __shfl_down_sync(0xFFFFFFFFu, s3, off);
    }

    __shared__ float sh1[4], sh2[4], sh3[4];
    const int warp = tid >> 5;
    const int lane = tid & 31;
    if (lane == 0) { sh1[warp] = s1; sh2[warp] = s2; sh3[warp] = s3; }
    __syncthreads();

    if (tid == 0) {
        float S1 = sh1[0] + sh1[1] + sh1[2] + sh1[3];
        float S2 = sh2[0] + sh2[1] + sh2[2] + sh2[3];
        float S3 = sh3[0] + sh3[1] + sh3[2] + sh3[3];
        // per_seg = (log(S1) - S3/S2) / scope[seg]
        float val = (__logf(S1) - S3 / S2) / (float)scope[seg];
        // Fire-and-forget RED.ADD: result unused -> no round-trip, CTA retires
        // immediately like a plain store.
        atomicAdd(&g_accum, val);
    }
}

// ---------------------------------------------------------------------------
// Kernel 2: trivial finalize, launched with PDL so it is resident during
// kernel 1 and starts the moment kernel 1 completes (hides the ~4.7us
// serialized launch/ramp floor of a dependent kernel).
// ---------------------------------------------------------------------------
__global__ __launch_bounds__(32) void listnet_finalize_kernel(
    float* __restrict__ out, int num_seg)
{
    // Wait for the upstream (streaming) kernel's grid to fully complete —
    // all REDs are then globally visible.
    cudaGridDependencySynchronize();
    if (threadIdx.x == 0) {
        out[0] = g_accum / (float)num_seg;
        g_accum = 0.0f;                    // reset for the next graph replay
    }
}

extern "C" void kernel_launch(void* const* d_in, const int* in_sizes, int n_in,
                              void* d_out, int out_size)
{
    // metadata order: mean (N), variance (N), scope (NUM_SEG), targets (N)
    const float* mean     = (const float*)d_in[0];
    const float* variance = (const float*)d_in[1];
    const int*   scope    = (const int*)  d_in[2];
    const float* targets  = (const float*)d_in[3];
    float* out = (float*)d_out;

    const int n       = in_sizes[0];
    const int num_seg = in_sizes[2];
    const int seg_len = n / num_seg;   // 512 for this dataset

    listnet_seg_kernel<<<num_seg, 128>>>(mean, variance, targets, scope, seg_len);

    // Finalize with Programmatic Dependent Launch: overlaps its launch/ramp
    // with kernel 1's execution; cudaGridDependencySynchronize() inside the
    // kernel provides the actual data dependency.
    cudaLaunchConfig_t cfg = {};
    cfg.gridDim  = dim3(1, 1, 1);
    cfg.blockDim = dim3(32, 1, 1);
    cfg.dynamicSmemBytes = 0;
    cfg.stream = (cudaStream_t)0;          // legacy default stream (captured)
    cudaLaunchAttribute attrs[1];
    attrs[0].id = cudaLaunchAttributeProgrammaticStreamSerialization;
    attrs[0].val.programmaticStreamSerializationAllowed = 1;
    cfg.attrs = attrs;
    cfg.numAttrs = 1;
    cudaLaunchKernelEx(&cfg, listnet_finalize_kernel, out, num_seg);
}

// round 12
// speedup vs baseline: 1.7571x; 1.7571x over previous
#include <cuda_runtime.h>
#include <cuda_bf16.h>

// 128 accumulator slots, each on its own 128-byte L2 line to avoid any
// single-address atomic serialization. Zero-initialized; finalize kernel
// re-zeroes them every launch so CUDA-graph replays are deterministic.
#define NSLOTS 128
__device__ float g_partial[NSLOTS][32];   // [slot][pad] — use [slot][0]

// ---------------------------------------------------------------------------
// Kernel 1: R1 streaming shape (proven ~6.6 TB/s): one CTA per segment,
// 128 threads, 3 front-batched LDG.128 per thread. Tail = ONE fire-and-forget
// RED.ADD per CTA to an ADDRESS-SPREAD slot (bid & 127): distinct L2 lines,
// <=128 ops per slot -> no serialization backpressure.
// ---------------------------------------------------------------------------
__global__ __launch_bounds__(128, 16) void listnet_seg_kernel(
    const float* __restrict__ mean,
    const float* __restrict__ variance,
    const float* __restrict__ targets,
    const int*   __restrict__ scope,
    int seg_len)
{
    const int seg = blockIdx.x;
    const int tid = threadIdx.x;           // 0..127
    const long long base = (long long)seg * seg_len;

    const float4* __restrict__ m4 = reinterpret_cast<const float4*>(mean + base);
    const float4* __restrict__ v4 = reinterpret_cast<const float4*>(variance + base);
    const float4* __restrict__ t4 = reinterpret_cast<const float4*>(targets + base);

    float s1 = 0.0f;  // sum exp(a),  a = x + 0.5 y
    float s2 = 0.0f;  // sum exp(t)
    float s3 = 0.0f;  // sum exp(t) * b,  b = x - 0.5 y

    const int nvec = seg_len >> 2;         // float4s per segment (128 for 512)
    for (int i = tid; i < nvec; i += 128) {
        float4 m = m4[i];
        float4 v = v4[i];
        float4 t = t4[i];

        { float h = 0.5f * v.x; float a = m.x + h, b = m.x - h;
          float ea = __expf(a), et = __expf(t.x);
          s1 += ea; s2 += et; s3 += et * b; }
        { float h = 0.5f * v.y; float a = m.y + h, b = m.y - h;
          float ea = __expf(a), et = __expf(t.y);
          s1 += ea; s2 += et; s3 += et * b; }
        { float h = 0.5f * v.z; float a = m.z + h, b = m.z - h;
          float ea = __expf(a), et = __expf(t.z);
          s1 += ea; s2 += et; s3 += et * b; }
        { float h = 0.5f * v.w; float a = m.w + h, b = m.w - h;
          float ea = __expf(a), et = __expf(t.w);
          s1 += ea; s2 += et; s3 += et * b; }
    }

    // Warp reduction (3 values)
    #pragma unroll
    for (int off = 16; off > 0; off >>= 1) {
        s1 += __shfl_down_sync(0xFFFFFFFFu, s1, off);
        s2 += __shfl_down_sync(0xFFFFFFFFu, s2, off);
        s3 += __shfl_down_sync(0xFFFFFFFFu, s3, off);
    }

    __shared__ float sh1[4], sh2[4], sh3[4];
    const int warp = tid >> 5;
    const int lane = tid & 31;
    if (lane == 0) { sh1[warp] = s1; sh2[warp] = s2; sh3[warp] = s3; }
    __syncthreads();

    if (tid == 0) {
        float S1 = sh1[0] + sh1[1] + sh1[2] + sh1[3];
        float S2 = sh2[0] + sh2[1] + sh2[2] + sh2[3];
        float S3 = sh3[0] + sh3[1] + sh3[2] + sh3[3];
        // per_seg = (log(S1) - S3/S2) / scope[seg]
        float val = (__logf(S1) - S3 / S2) / (float)scope[seg];
        // Fire-and-forget RED.ADD to a spread slot (own 128B line).
        atomicAdd(&g_partial[seg & (NSLOTS - 1)][0], val);
    }
}

// ---------------------------------------------------------------------------
// Kernel 2: 1-warp finalize, launched with PDL so its ramp overlaps kernel 1.
// Reads the 128 slots, reduces, writes out, and re-zeroes the slots.
// ---------------------------------------------------------------------------
__global__ __launch_bounds__(32) void listnet_finalize_kernel(
    float* __restrict__ out, int num_seg)
{
    // Block until the streaming grid is complete and its REDs are visible.
    cudaGridDependencySynchronize();

    const int lane = threadIdx.x;          // 0..31
    float s = 0.0f;
    #pragma unroll
    for (int k = 0; k < NSLOTS / 32; k++) {
        int slot = lane + k * 32;
        s += g_partial[slot][0];
        g_partial[slot][0] = 0.0f;         // reset for next graph replay
    }

    #pragma unroll
    for (int off = 16; off > 0; off >>= 1)
        s += __shfl_down_sync(0xFFFFFFFFu, s, off);

    if (lane == 0)
        out[0] = s / (float)num_seg;
}

extern "C" void kernel_launch(void* const* d_in, const int* in_sizes, int n_in,
                              void* d_out, int out_size)
{
    // metadata order: mean (N), variance (N), scope (NUM_SEG), targets (N)
    const float* mean     = (const float*)d_in[0];
    const float* variance = (const float*)d_in[1];
    const int*   scope    = (const int*)  d_in[2];
    const float* targets  = (const float*)d_in[3];
    float* out = (float*)d_out;

    const int n       = in_sizes[0];
    const int num_seg = in_sizes[2];
    const int seg_len = n / num_seg;   // 512 for this dataset

    listnet_seg_kernel<<<num_seg, 128>>>(mean, variance, targets, scope, seg_len);

    // Finalize with Programmatic Dependent Launch: launch ramp overlaps
    // kernel 1; cudaGridDependencySynchronize() provides the data dependency.
    cudaLaunchConfig_t cfg = {};
    cfg.gridDim  = dim3(1, 1, 1);
    cfg.blockDim = dim3(32, 1, 1);
    cfg.dynamicSmemBytes = 0;
    cfg.stream = (cudaStream_t)0;          // legacy default stream (captured)
    cudaLaunchAttribute attrs[1];
    attrs[0].id = cudaLaunchAttributeProgrammaticStreamSerialization;
    attrs[0].val.programmaticStreamSerializationAllowed = 1;
    cfg.attrs = attrs;
    cfg.numAttrs = 1;
    cudaLaunchKernelEx(&cfg, listnet_finalize_kernel, out, num_seg);
}